// round 2
// baseline (speedup 1.0000x reference)
#include <cuda_runtime.h>

// Problem: B=16, mask (16,2,512,512) -bilinear x2-> (16,2,1024,1024)
// fused = x_mask*xl + y_mask*yl  (3 channels, 1024x1024)
// out[o] = relu(sum_i cw[o][i]*fused[i] + cb[o])
// d_out layout: out (16*3*1024*1024) | x_mask (16*1024*1024) | y_mask (16*1024*1024)

#define HS 512
#define WS 512
#define HU 1024
#define WU 1024

__global__ __launch_bounds__(256)
void fused_upsample_blend_conv(const float* __restrict__ mask,
                               const float* __restrict__ xl,
                               const float* __restrict__ yl,
                               const float* __restrict__ cw,
                               const float* __restrict__ cb,
                               float* __restrict__ out)
{
    const int idx = blockIdx.x * blockDim.x + threadIdx.x;
    // idx -> (b, h, w4): w4 in [0,256), h in [0,1024), b in [0,16)
    const int w4 = idx & 255;
    const int h  = (idx >> 8) & 1023;
    const int b  = idx >> 18;

    // ---- vertical source rows (jax half-pixel bilinear, scale 2) ----
    // out row h samples source at 0.5*h - 0.25:
    //   h even=2j: 0.75*row[j] + 0.25*row[j-1]   (clamped)
    //   h odd =2j+1: 0.75*row[j] + 0.25*row[j+1] (clamped)
    const int hj = h >> 1;
    const int r1 = hj;                                        // weight 0.75
    const int r2 = (h & 1) ? min(hj + 1, HS - 1) : max(hj - 1, 0); // weight 0.25

    // ---- horizontal source columns for 4 outputs starting at w = 4*w4 ----
    const int k0  = w4 << 1;               // even source col (0..510)
    const int cm1 = max(k0 - 1, 0);
    const int c0  = k0;
    const int c1  = k0 + 1;
    const int cp2 = min(k0 + 2, WS - 1);

    const float* m0r1 = mask + (((long)b * 2 + 0) * HS + r1) * WS;
    const float* m0r2 = mask + (((long)b * 2 + 0) * HS + r2) * WS;
    const float* m1r1 = mask + (((long)b * 2 + 1) * HS + r1) * WS;
    const float* m1r2 = mask + (((long)b * 2 + 1) * HS + r2) * WS;

    // vertical interp at 4 source columns, both mask channels
    const float v0a = 0.75f * __ldg(m0r1 + cm1) + 0.25f * __ldg(m0r2 + cm1);
    const float v0b = 0.75f * __ldg(m0r1 + c0 ) + 0.25f * __ldg(m0r2 + c0 );
    const float v0c = 0.75f * __ldg(m0r1 + c1 ) + 0.25f * __ldg(m0r2 + c1 );
    const float v0d = 0.75f * __ldg(m0r1 + cp2) + 0.25f * __ldg(m0r2 + cp2);

    const float v1a = 0.75f * __ldg(m1r1 + cm1) + 0.25f * __ldg(m1r2 + cm1);
    const float v1b = 0.75f * __ldg(m1r1 + c0 ) + 0.25f * __ldg(m1r2 + c0 );
    const float v1c = 0.75f * __ldg(m1r1 + c1 ) + 0.25f * __ldg(m1r2 + c1 );
    const float v1d = 0.75f * __ldg(m1r1 + cp2) + 0.25f * __ldg(m1r2 + cp2);

    // horizontal interp: out 2k -> 0.75*v[k]+0.25*v[k-1]; out 2k+1 -> 0.75*v[k]+0.25*v[k+1]
    float4 xm, ym;
    xm.x = 0.75f * v0b + 0.25f * v0a;
    xm.y = 0.75f * v0b + 0.25f * v0c;
    xm.z = 0.75f * v0c + 0.25f * v0b;
    xm.w = 0.75f * v0c + 0.25f * v0d;

    ym.x = 0.75f * v1b + 0.25f * v1a;
    ym.y = 0.75f * v1b + 0.25f * v1c;
    ym.z = 0.75f * v1c + 0.25f * v1b;
    ym.w = 0.75f * v1c + 0.25f * v1d;

    // ---- load xl / yl float4 (3 channels each) ----
    const int w = w4 << 2;
    const long plane = (long)HU * WU;                       // 1048576
    const long pix   = (long)h * WU + w;

    const float4 a0 = __ldg((const float4*)(xl + ((long)b * 3 + 0) * plane + pix));
    const float4 a1 = __ldg((const float4*)(xl + ((long)b * 3 + 1) * plane + pix));
    const float4 a2 = __ldg((const float4*)(xl + ((long)b * 3 + 2) * plane + pix));
    const float4 c0v = __ldg((const float4*)(yl + ((long)b * 3 + 0) * plane + pix));
    const float4 c1v = __ldg((const float4*)(yl + ((long)b * 3 + 1) * plane + pix));
    const float4 c2v = __ldg((const float4*)(yl + ((long)b * 3 + 2) * plane + pix));

    // fused channels (per lane)
    float4 f0, f1, f2;
    f0.x = xm.x * a0.x + ym.x * c0v.x;  f0.y = xm.y * a0.y + ym.y * c0v.y;
    f0.z = xm.z * a0.z + ym.z * c0v.z;  f0.w = xm.w * a0.w + ym.w * c0v.w;
    f1.x = xm.x * a1.x + ym.x * c1v.x;  f1.y = xm.y * a1.y + ym.y * c1v.y;
    f1.z = xm.z * a1.z + ym.z * c1v.z;  f1.w = xm.w * a1.w + ym.w * c1v.w;
    f2.x = xm.x * a2.x + ym.x * c2v.x;  f2.y = xm.y * a2.y + ym.y * c2v.y;
    f2.z = xm.z * a2.z + ym.z * c2v.z;  f2.w = xm.w * a2.w + ym.w * c2v.w;

    // conv weights (uniform broadcast loads, L1-resident)
    const float w00 = __ldg(cw + 0), w01 = __ldg(cw + 1), w02 = __ldg(cw + 2);
    const float w10 = __ldg(cw + 3), w11 = __ldg(cw + 4), w12 = __ldg(cw + 5);
    const float w20 = __ldg(cw + 6), w21 = __ldg(cw + 7), w22 = __ldg(cw + 8);
    const float bb0 = __ldg(cb + 0), bb1 = __ldg(cb + 1), bb2 = __ldg(cb + 2);

    float4 o0, o1, o2;
    o0.x = fmaxf(w00 * f0.x + w01 * f1.x + w02 * f2.x + bb0, 0.f);
    o0.y = fmaxf(w00 * f0.y + w01 * f1.y + w02 * f2.y + bb0, 0.f);
    o0.z = fmaxf(w00 * f0.z + w01 * f1.z + w02 * f2.z + bb0, 0.f);
    o0.w = fmaxf(w00 * f0.w + w01 * f1.w + w02 * f2.w + bb0, 0.f);

    o1.x = fmaxf(w10 * f0.x + w11 * f1.x + w12 * f2.x + bb1, 0.f);
    o1.y = fmaxf(w10 * f0.y + w11 * f1.y + w12 * f2.y + bb1, 0.f);
    o1.z = fmaxf(w10 * f0.z + w11 * f1.z + w12 * f2.z + bb1, 0.f);
    o1.w = fmaxf(w10 * f0.w + w11 * f1.w + w12 * f2.w + bb1, 0.f);

    o2.x = fmaxf(w20 * f0.x + w21 * f1.x + w22 * f2.x + bb2, 0.f);
    o2.y = fmaxf(w20 * f0.y + w21 * f1.y + w22 * f2.y + bb2, 0.f);
    o2.z = fmaxf(w20 * f0.z + w21 * f1.z + w22 * f2.z + bb2, 0.f);
    o2.w = fmaxf(w20 * f0.w + w21 * f1.w + w22 * f2.w + bb2, 0.f);

    // ---- stores ----
    const long XM_OFF = 48L * plane;    // after out (16*3 planes)
    const long YM_OFF = 64L * plane;    // after x_mask (16 planes)

    *(float4*)(out + ((long)b * 3 + 0) * plane + pix) = o0;
    *(float4*)(out + ((long)b * 3 + 1) * plane + pix) = o1;
    *(float4*)(out + ((long)b * 3 + 2) * plane + pix) = o2;
    *(float4*)(out + XM_OFF + (long)b * plane + pix)  = xm;
    *(float4*)(out + YM_OFF + (long)b * plane + pix)  = ym;
}

extern "C" void kernel_launch(void* const* d_in, const int* in_sizes, int n_in,
                              void* d_out, int out_size)
{
    const float* mask = (const float*)d_in[0];
    const float* xl   = (const float*)d_in[1];
    const float* yl   = (const float*)d_in[2];
    const float* cw   = (const float*)d_in[3];
    const float* cb   = (const float*)d_in[4];
    float* out = (float*)d_out;

    // 16 * 1024 * 256 threads total, 256 per block -> 16384 blocks
    const int total = 16 * 1024 * 256;
    fused_upsample_blend_conv<<<total / 256, 256>>>(mask, xl, yl, cw, cb, out);
}